// round 4
// baseline (speedup 1.0000x reference)
#include <cuda_runtime.h>
#include <cuda_bf16.h>
#include <cstdint>

#define BB 32
#define SS 512
#define DD 768

static const long N_SD = (long)BB * SS * DD;   // 12,582,912

// ---------------- scratch (static device globals; no allocations) ----------
__device__ __nv_bfloat16 g_x1h [BB * SS * DD];
__device__ __nv_bfloat16 g_x1l [BB * SS * DD];
__device__ __nv_bfloat16 g_WcTh[DD * DD];
__device__ __nv_bfloat16 g_WcTl[DD * DD];
__device__ __nv_bfloat16 g_x2rh[BB * SS * DD];   // [t][e] = x2flat[e*S+t]
__device__ __nv_bfloat16 g_x2rl[BB * SS * DD];
__device__ __nv_bfloat16 g_x2Th[BB * DD * SS];   // [d][t] = x2[t][d]
__device__ __nv_bfloat16 g_x2Tl[BB * DD * SS];
__device__ __nv_bfloat16 g_x1Th[BB * DD * SS];   // [d][s] = x1[s][d]
__device__ __nv_bfloat16 g_x1Tl[BB * DD * SS];
__device__ __nv_bfloat16 g_x1wh[BB * SS * DD];
__device__ __nv_bfloat16 g_x1wl[BB * SS * DD];
__device__ __nv_bfloat16 g_P1h [BB * SS * SS];
__device__ __nv_bfloat16 g_P1l [BB * SS * SS];
__device__ __nv_bfloat16 g_P2Th[BB * SS * SS];   // [t][s]
__device__ __nv_bfloat16 g_P2Tl[BB * SS * SS];
__device__ float g_A  [BB * SS * SS];            // fp32 logits
__device__ float g_rowmax[BB * SS];
__device__ float g_rowrs [BB * SS];
__device__ float g_colmax[BB * SS];
__device__ float g_colrs [BB * SS];
__device__ float g_bias1 [BB * SS];
__device__ float g_bias2 [BB * SS];

// ---------------- helpers ----------------------------------------------------
__device__ __forceinline__ uint32_t smem_to_u32(const void* p) {
    uint32_t a;
    asm("{ .reg .u64 t; cvta.to.shared.u64 t, %1; cvt.u32.u64 %0, t; }" : "=r"(a) : "l"(p));
    return a;
}
__device__ __forceinline__ void cp_async16(uint32_t dst, const void* src) {
    asm volatile("cp.async.cg.shared.global [%0], [%1], 16;" :: "r"(dst), "l"(src));
}
__device__ __forceinline__ void ldsm_x4(uint32_t* r, uint32_t addr) {
    asm volatile("ldmatrix.sync.aligned.m8n8.x4.shared.b16 {%0,%1,%2,%3}, [%4];"
                 : "=r"(r[0]), "=r"(r[1]), "=r"(r[2]), "=r"(r[3]) : "r"(addr));
}
__device__ __forceinline__ void mma16816(float* d, const uint32_t* a, const uint32_t* b) {
    asm volatile(
        "mma.sync.aligned.m16n8k16.row.col.f32.bf16.bf16.f32 "
        "{%0,%1,%2,%3}, {%4,%5,%6,%7}, {%8,%9}, {%0,%1,%2,%3};"
        : "+f"(d[0]), "+f"(d[1]), "+f"(d[2]), "+f"(d[3])
        : "r"(a[0]), "r"(a[1]), "r"(a[2]), "r"(a[3]), "r"(b[0]), "r"(b[1]));
}

union Pack4 { __nv_bfloat16 b[4]; uint2 u; };
__device__ __forceinline__ void split1(float v, __nv_bfloat16& h, __nv_bfloat16& l) {
    h = __float2bfloat16_rn(v);
    l = __float2bfloat16_rn(v - __bfloat162float(h));
}

// ---------------- convert: fp32 -> bf16 hi/lo (elementwise) ------------------
__global__ void conv_hl(const float4* __restrict__ in,
                        __nv_bfloat16* __restrict__ oh, __nv_bfloat16* __restrict__ ol)
{
    long i = (long)blockIdx.x * 256 + threadIdx.x;
    float4 v = in[i];
    Pack4 h, l;
    split1(v.x, h.b[0], l.b[0]);
    split1(v.y, h.b[1], l.b[1]);
    split1(v.z, h.b[2], l.b[2]);
    split1(v.w, h.b[3], l.b[3]);
    ((uint2*)oh)[i] = h.u;
    ((uint2*)ol)[i] = l.u;
}

// ---------------- transpose + split: in[R][C] -> out[C][R] hi/lo -------------
__global__ void transpose_hl(const float* __restrict__ in, long sIn, int R, int C,
                             __nv_bfloat16* __restrict__ oh, __nv_bfloat16* __restrict__ ol,
                             long sOut)
{
    __shared__ float t[32][33];
    in += (long)blockIdx.z * sIn;
    oh += (long)blockIdx.z * sOut;
    ol += (long)blockIdx.z * sOut;
    int c0 = blockIdx.x * 32, r0 = blockIdx.y * 32;
    int tx = threadIdx.x & 31, ty = threadIdx.x >> 5;  // 256 threads -> ty 0..7
    #pragma unroll
    for (int j = 0; j < 4; j++)
        t[ty + j * 8][tx] = in[(long)(r0 + ty + j * 8) * C + c0 + tx];
    __syncthreads();
    int c = threadIdx.x >> 3, g = threadIdx.x & 7;
    int rr = g * 4;
    Pack4 h, l;
    #pragma unroll
    for (int q = 0; q < 4; q++) split1(t[rr + q][c], h.b[q], l.b[q]);
    *(uint2*)(oh + (long)(c0 + c) * R + r0 + rr) = h.u;
    *(uint2*)(ol + (long)(c0 + c) * R + r0 + rr) = l.u;
}

// ---------------- bias: bias1[b,s] = x1[b,s,:].W1 ; bias2[b,t] = x2[b,t,:].W2
__global__ void bias_kernel(const float* __restrict__ x1, const float* __restrict__ x2,
                            const float* __restrict__ W1, const float* __restrict__ W2)
{
    int warp = (blockIdx.x * blockDim.x + threadIdx.x) >> 5;
    int lane = threadIdx.x & 31;
    const int total = BB * SS;
    const float* x; const float* W; float* out; int row;
    if (warp < total) { x = x1; W = W1; out = g_bias1; row = warp; }
    else              { x = x2; W = W2; out = g_bias2; row = warp - total; }
    const float4* xr = (const float4*)(x + (long)row * DD);
    const float4* W4 = (const float4*)W;
    float s = 0.f;
    #pragma unroll
    for (int i = lane; i < DD / 4; i += 32) {
        float4 a = xr[i], w = W4[i];
        s += a.x * w.x + a.y * w.y + a.z * w.z + a.w * w.w;
    }
    #pragma unroll
    for (int o = 16; o; o >>= 1) s += __shfl_xor_sync(0xffffffffu, s, o);
    if (lane == 0) out[row] = s;
}

// ---------------- mma.sync split-bf16 GEMM -----------------------------------
// C[m][n] = sum_k (Ah+Al)[m][k]*(Bh+Bl)[n][k]  (3-term: hh + hl + lh)
// Block tile 128x256, BK=32, 8 warps (2M x 4N), warp tile 64x64.
// EPI 0: fp32 C.  EPI 1: bf16 hi/lo C.  EPI 2: fp32 C + biasR + biasC.
#define RSTRIDE  80                     // bytes per smem row (32 bf16 pad-> 40)
#define TILEA    (128 * RSTRIDE)        // 10240 B
#define TILEB_   (256 * RSTRIDE)        // 20480 B
#define STAGEB   (2 * TILEA + 2 * TILEB_) // 61440 B
#define SMEM_GEMM (2 * STAGEB)          // 122880 B

template <int EPI>
__global__ void __launch_bounds__(256, 1) gemm_tc(
    const __nv_bfloat16* __restrict__ Ah, const __nv_bfloat16* __restrict__ Al, long sA, int lda,
    const __nv_bfloat16* __restrict__ Bh, const __nv_bfloat16* __restrict__ Bl, long sB, int ldb,
    int K,
    float* __restrict__ C, __nv_bfloat16* __restrict__ Ch, __nv_bfloat16* __restrict__ Cl,
    long sC, int ldc,
    const float* __restrict__ biasR, const float* __restrict__ biasC, int Mtot, int Ntot)
{
    extern __shared__ char smem[];
    const uint32_t sbase = smem_to_u32(smem);
    const int tid = threadIdx.x;
    const int lane = tid & 31;
    const int wm = (tid >> 5) >> 2, wn = (tid >> 5) & 3;   // 2 x 4 warp grid
    const int bm = blockIdx.y * 128, bn = blockIdx.x * 256, bz = blockIdx.z;

    const __nv_bfloat16* a0 = Ah + (long)bz * sA;
    const __nv_bfloat16* a1 = Al + (long)bz * sA;
    const __nv_bfloat16* b0 = Bh + (long)bz * sB;
    const __nv_bfloat16* b1 = Bl + (long)bz * sB;

    const int ldrow = tid >> 2;          // 0..63
    const int lds   = tid & 3;           // 16B seg within 64B of K-chunk row

    float acc[4][8][4];
    #pragma unroll
    for (int i = 0; i < 4; i++)
        #pragma unroll
        for (int j = 0; j < 8; j++)
            #pragma unroll
            for (int q = 0; q < 4; q++) acc[i][j][q] = 0.f;

    const int NC = K >> 5;

    // stage layout: [Ah 10240 | Al 10240 | Bh 20480 | Bl 20480]
    #define LOAD_STAGE(cc, st) do {                                              \
        uint32_t dst0 = sbase + (st) * STAGEB;                                   \
        int k0 = (cc) << 5;                                                      \
        _Pragma("unroll")                                                        \
        for (int q = 0; q < 12; q++) {                                           \
            const int isB  = (q >= 4);                                           \
            const int lo   = isB ? ((q - 4) >> 2) : (q >> 1);                    \
            const int row  = isB ? (((q - 4) & 3) << 6) + ldrow                  \
                                 : ((q & 1) << 6) + ldrow;                       \
            const __nv_bfloat16* sp = isB ? (lo ? b1 : b0) : (lo ? a1 : a0);     \
            const int rb = isB ? bn : bm;                                        \
            const int ld = isB ? ldb : lda;                                      \
            const uint32_t toff = isB ? (2 * TILEA + lo * TILEB_)                \
                                      : (lo * TILEA);                            \
            cp_async16(dst0 + toff + row * RSTRIDE + lds * 16,                   \
                       sp + (long)(rb + row) * ld + k0 + lds * 8);               \
        }                                                                        \
        asm volatile("cp.async.commit_group;");                                  \
    } while (0)

    LOAD_STAGE(0, 0);

    const int lr = lane & 15;
    const int lc = (lane >> 4) << 3;

    for (int c = 0; c < NC; c++) {
        if (c + 1 < NC) {
            LOAD_STAGE(c + 1, (c + 1) & 1);
            asm volatile("cp.async.wait_group 1;");
        } else {
            asm volatile("cp.async.wait_group 0;");
        }
        __syncthreads();

        uint32_t sAh = sbase + (c & 1) * STAGEB;
        uint32_t sAl = sAh + TILEA;
        uint32_t sBh = sAh + 2 * TILEA;
        uint32_t sBl = sBh + TILEB_;

        #pragma unroll
        for (int kk = 0; kk < 2; kk++) {
            uint32_t fa_h[4][4], fa_l[4][4];
            #pragma unroll
            for (int mm = 0; mm < 4; mm++) {
                uint32_t off = (uint32_t)(wm * 64 + mm * 16 + lr) * RSTRIDE
                             + (uint32_t)(kk * 16 + lc) * 2;
                ldsm_x4(fa_h[mm], sAh + off);
                ldsm_x4(fa_l[mm], sAl + off);
            }
            #pragma unroll
            for (int nn = 0; nn < 4; nn++) {
                uint32_t fb_h[4], fb_l[4];
                uint32_t off = (uint32_t)(wn * 64 + nn * 16 + lr) * RSTRIDE
                             + (uint32_t)(kk * 16 + lc) * 2;
                ldsm_x4(fb_h, sBh + off);
                ldsm_x4(fb_l, sBl + off);
                #pragma unroll
                for (int mm = 0; mm < 4; mm++) {
                    #pragma unroll
                    for (int n2 = 0; n2 < 2; n2++) {
                        uint32_t bh2[2] = { fb_h[n2], fb_h[n2 + 2] };
                        uint32_t bl2[2] = { fb_l[n2], fb_l[n2 + 2] };
                        float* d = acc[mm][nn * 2 + n2];
                        mma16816(d, fa_h[mm], bh2);
                        mma16816(d, fa_h[mm], bl2);
                        mma16816(d, fa_l[mm], bh2);
                    }
                }
            }
        }
        __syncthreads();
    }

    // ---- epilogue
    const int er0 = bm + wm * 64 + (lane >> 2);
    const int ec0 = bn + wn * 64 + ((lane & 3) << 1);
    #pragma unroll
    for (int mm = 0; mm < 4; mm++) {
        #pragma unroll
        for (int nt = 0; nt < 8; nt++) {
            int row = er0 + mm * 16;
            int col = ec0 + nt * 8;
            float v0 = acc[mm][nt][0], v1 = acc[mm][nt][1];
            float v2 = acc[mm][nt][2], v3 = acc[mm][nt][3];
            if (EPI == 1) {
                __nv_bfloat16 h0, l0, h1, l1;
                long o = (long)bz * sC + (long)row * ldc + col;
                split1(v0, h0, l0); split1(v1, h1, l1);
                *(__nv_bfloat162*)(Ch + o) = __nv_bfloat162(h0, h1);
                *(__nv_bfloat162*)(Cl + o) = __nv_bfloat162(l0, l1);
                o += (long)8 * ldc;
                split1(v2, h0, l0); split1(v3, h1, l1);
                *(__nv_bfloat162*)(Ch + o) = __nv_bfloat162(h0, h1);
                *(__nv_bfloat162*)(Cl + o) = __nv_bfloat162(l0, l1);
            } else {
                if (EPI == 2) {
                    float bc0 = biasC[bz * Ntot + col], bc1 = biasC[bz * Ntot + col + 1];
                    float br0 = biasR[bz * Mtot + row], br8 = biasR[bz * Mtot + row + 8];
                    v0 += br0 + bc0; v1 += br0 + bc1;
                    v2 += br8 + bc0; v3 += br8 + bc1;
                }
                long o = (long)bz * sC + (long)row * ldc + col;
                *(float2*)(C + o) = make_float2(v0, v1);
                *(float2*)(C + o + (long)8 * ldc) = make_float2(v2, v3);
            }
        }
    }
}

// ---------------- softmax stats ---------------------------------------------
__global__ void row_stats_kernel()
{
    int row = blockIdx.x;
    const float4* a = (const float4*)(g_A + (long)row * SS);
    int tid = threadIdx.x;
    float4 v = a[tid];
    float m = fmaxf(fmaxf(v.x, v.y), fmaxf(v.z, v.w));
    #pragma unroll
    for (int o = 16; o; o >>= 1) m = fmaxf(m, __shfl_xor_sync(0xffffffffu, m, o));
    __shared__ float sm[4], ssum[4];
    int w = tid >> 5, l = tid & 31;
    if (l == 0) sm[w] = m;
    __syncthreads();
    m = fmaxf(fmaxf(sm[0], sm[1]), fmaxf(sm[2], sm[3]));
    float s = __expf(v.x - m) + __expf(v.y - m) + __expf(v.z - m) + __expf(v.w - m);
    #pragma unroll
    for (int o = 16; o; o >>= 1) s += __shfl_xor_sync(0xffffffffu, s, o);
    if (l == 0) ssum[w] = s;
    __syncthreads();
    s = ssum[0] + ssum[1] + ssum[2] + ssum[3];
    if (tid == 0) { g_rowmax[row] = m; g_rowrs[row] = 1.0f / s; }
}

__global__ void col_stats_kernel()
{
    int b = blockIdx.x >> 2;
    int t = ((blockIdx.x & 3) << 7) + threadIdx.x;
    const float* a = g_A + (long)b * SS * SS + t;
    float m = -1e30f;
    #pragma unroll 8
    for (int s = 0; s < SS; s++) m = fmaxf(m, a[(long)s * SS]);
    float sum = 0.f;
    #pragma unroll 8
    for (int s = 0; s < SS; s++) sum += __expf(a[(long)s * SS] - m);
    g_colmax[b * SS + t] = m;
    g_colrs [b * SS + t] = 1.0f / sum;
}

// ---------------- probabilities: P1 (hi/lo) and P2^T (hi/lo) -----------------
__global__ void prob_kernel()
{
    __shared__ float p2t[64 * 65];
    int b = blockIdx.z;
    int bs0 = blockIdx.y * 64, bt0 = blockIdx.x * 64;
    const float* A = g_A + (long)b * SS * SS;
    int tid = threadIdx.x;

    #pragma unroll
    for (int it = 0; it < 4; it++) {
        int idx = tid + it * 256;
        int r = idx >> 4, c4 = idx & 15;
        int s = bs0 + r;
        float4 v = *(const float4*)(A + (long)s * SS + bt0 + c4 * 4);
        float rm = g_rowmax[b * SS + s];
        float rr = g_rowrs [b * SS + s];
        const float4 cm = *(const float4*)(g_colmax + b * SS + bt0 + c4 * 4);
        const float4 cr = *(const float4*)(g_colrs  + b * SS + bt0 + c4 * 4);
        float p1v[4] = { __expf(v.x - cm.x) * cr.x, __expf(v.y - cm.y) * cr.y,
                         __expf(v.z - cm.z) * cr.z, __expf(v.w - cm.w) * cr.w };
        float p2v[4] = { __expf(v.x - rm) * rr, __expf(v.y - rm) * rr,
                         __expf(v.z - rm) * rr, __expf(v.w - rm) * rr };
        Pack4 h, l;
        #pragma unroll
        for (int q = 0; q < 4; q++) split1(p1v[q], h.b[q], l.b[q]);
        long o1 = (long)b * SS * SS + (long)s * SS + bt0 + c4 * 4;
        *(uint2*)(g_P1h + o1) = h.u;
        *(uint2*)(g_P1l + o1) = l.u;
        #pragma unroll
        for (int q = 0; q < 4; q++) p2t[(c4 * 4 + q) * 65 + r] = p2v[q];
    }
    __syncthreads();
    int c = tid >> 2, g = tid & 3;
    #pragma unroll
    for (int j = 0; j < 4; j++) {
        int rr0 = g * 16 + j * 4;
        Pack4 h, l;
        #pragma unroll
        for (int q = 0; q < 4; q++) split1(p2t[c * 65 + rr0 + q], h.b[q], l.b[q]);
        long o = (long)b * SS * SS + (long)(bt0 + c) * SS + bs0 + rr0;
        *(uint2*)(g_P2Th + o) = h.u;
        *(uint2*)(g_P2Tl + o) = l.u;
    }
}

// ---------------- launch -----------------------------------------------------
extern "C" void kernel_launch(void* const* d_in, const int* in_sizes, int n_in,
                              void* d_out, int out_size)
{
    const float* x1 = (const float*)d_in[0];
    const float* x2 = (const float*)d_in[1];
    const float* Wc = (const float*)d_in[2];
    const float* W1 = (const float*)d_in[3];
    const float* W2 = (const float*)d_in[4];
    float* out1 = (float*)d_out;
    float* out2 = out1 + N_SD;

    __nv_bfloat16 *x1h, *x1l, *WcTh, *WcTl, *x2rh, *x2rl, *x2Th, *x2Tl, *x1Th, *x1Tl;
    __nv_bfloat16 *x1wh, *x1wl, *P1h, *P1l, *P2Th, *P2Tl;
    float *pA, *pb1, *pb2;
    cudaGetSymbolAddress((void**)&x1h,  g_x1h);
    cudaGetSymbolAddress((void**)&x1l,  g_x1l);
    cudaGetSymbolAddress((void**)&WcTh, g_WcTh);
    cudaGetSymbolAddress((void**)&WcTl, g_WcTl);
    cudaGetSymbolAddress((void**)&x2rh, g_x2rh);
    cudaGetSymbolAddress((void**)&x2rl, g_x2rl);
    cudaGetSymbolAddress((void**)&x2Th, g_x2Th);
    cudaGetSymbolAddress((void**)&x2Tl, g_x2Tl);
    cudaGetSymbolAddress((void**)&x1Th, g_x1Th);
    cudaGetSymbolAddress((void**)&x1Tl, g_x1Tl);
    cudaGetSymbolAddress((void**)&x1wh, g_x1wh);
    cudaGetSymbolAddress((void**)&x1wl, g_x1wl);
    cudaGetSymbolAddress((void**)&P1h,  g_P1h);
    cudaGetSymbolAddress((void**)&P1l,  g_P1l);
    cudaGetSymbolAddress((void**)&P2Th, g_P2Th);
    cudaGetSymbolAddress((void**)&P2Tl, g_P2Tl);
    cudaGetSymbolAddress((void**)&pA,   g_A);
    cudaGetSymbolAddress((void**)&pb1,  g_bias1);
    cudaGetSymbolAddress((void**)&pb2,  g_bias2);

    cudaFuncSetAttribute(gemm_tc<0>, cudaFuncAttributeMaxDynamicSharedMemorySize, SMEM_GEMM);
    cudaFuncSetAttribute(gemm_tc<1>, cudaFuncAttributeMaxDynamicSharedMemorySize, SMEM_GEMM);
    cudaFuncSetAttribute(gemm_tc<2>, cudaFuncAttributeMaxDynamicSharedMemorySize, SMEM_GEMM);

    const long sSD = (long)SS * DD;
    const long sSq = (long)SS * SS;

    // converts / transposes
    conv_hl<<<(int)(N_SD / 4 / 256), 256>>>((const float4*)x1, x1h, x1l);
    transpose_hl<<<dim3(DD / 32, DD / 32, 1), 256>>>(Wc, 0, DD, DD, WcTh, WcTl, 0);
    transpose_hl<<<dim3(SS / 32, DD / 32, BB), 256>>>(x2, sSD, DD, SS, x2rh, x2rl, sSD);
    transpose_hl<<<dim3(DD / 32, SS / 32, BB), 256>>>(x2, sSD, SS, DD, x2Th, x2Tl, sSD);
    transpose_hl<<<dim3(DD / 32, SS / 32, BB), 256>>>(x1, sSD, SS, DD, x1Th, x1Tl, sSD);
    bias_kernel<<<(2 * BB * SS) / 8, 256>>>(x1, x2, W1, W2);

    // G1: x1w = x1 @ Wc  (M=512, N=768, K=768) -> bf16 hi/lo epilogue
    gemm_tc<1><<<dim3(DD / 256, SS / 128, BB), 256, SMEM_GEMM>>>(
        x1h, x1l, sSD, DD, WcTh, WcTl, 0, DD, DD,
        nullptr, x1wh, x1wl, sSD, DD, nullptr, nullptr, SS, DD);

    // G3: A = x1w @ x2r^T + biases  (M=512, N=512, K=768) -> fp32 + bias
    gemm_tc<2><<<dim3(SS / 256, SS / 128, BB), 256, SMEM_GEMM>>>(
        x1wh, x1wl, sSD, DD, x2rh, x2rl, sSD, DD, DD,
        pA, nullptr, nullptr, sSq, SS, pb1, pb2, SS, SS);

    row_stats_kernel<<<BB * SS, 128>>>();
    col_stats_kernel<<<BB * 4, 128>>>();
    prob_kernel<<<dim3(SS / 64, SS / 64, BB), 256>>>();

    // G5: f_x1 = P1 @ x2  (M=512, N=768, K=512)
    gemm_tc<0><<<dim3(DD / 256, SS / 128, BB), 256, SMEM_GEMM>>>(
        P1h, P1l, sSq, SS, x2Th, x2Tl, sSD, SS, SS,
        out1, nullptr, nullptr, sSD, DD, nullptr, nullptr, SS, DD);

    // G6: f_x2 = P2^T @ x1  (M=512, N=768, K=512)
    gemm_tc<0><<<dim3(DD / 256, SS / 128, BB), 256, SMEM_GEMM>>>(
        P2Th, P2Tl, sSq, SS, x1Th, x1Tl, sSD, SS, SS,
        out2, nullptr, nullptr, sSD, DD, nullptr, nullptr, SS, DD);
}

// round 5
// speedup vs baseline: 1.1411x; 1.1411x over previous
#include <cuda_runtime.h>
#include <cuda_fp16.h>
#include <cstdint>

#define BB 32
#define SS 512
#define DD 768

static const long N_SD = (long)BB * SS * DD;   // 12,582,912

// ---------------- scratch (static device globals; no allocations) ----------
__device__ __half g_x1h [BB * SS * DD];
__device__ __half g_x1l [BB * SS * DD];
__device__ __half g_WcTh[DD * DD];
__device__ __half g_WcTl[DD * DD];
__device__ __half g_x2rh[BB * SS * DD];   // [t][e] = x2flat[e*S+t]
__device__ __half g_x2rl[BB * SS * DD];
__device__ __half g_x2Th[BB * DD * SS];   // [d][t] = x2[t][d]
__device__ __half g_x2Tl[BB * DD * SS];
__device__ __half g_x1Th[BB * DD * SS];   // [d][s] = x1[s][d]
__device__ __half g_x1Tl[BB * DD * SS];
__device__ __half g_x1wh[BB * SS * DD];
__device__ __half g_x1wl[BB * SS * DD];
__device__ __half g_P1  [BB * SS * SS];   // single-plane fp16 P1
__device__ __half g_P2T [BB * SS * SS];   // single-plane fp16 P2^T  [t][s]
__device__ float g_A  [BB * SS * SS];     // fp32 logits
__device__ float g_rowmax[BB * SS];
__device__ float g_rowrs [BB * SS];
__device__ float g_colmax[BB * SS];
__device__ float g_colrs [BB * SS];
__device__ float g_bias1 [BB * SS];
__device__ float g_bias2 [BB * SS];

// ---------------- helpers ----------------------------------------------------
__device__ __forceinline__ uint32_t smem_to_u32(const void* p) {
    uint32_t a;
    asm("{ .reg .u64 t; cvta.to.shared.u64 t, %1; cvt.u32.u64 %0, t; }" : "=r"(a) : "l"(p));
    return a;
}
__device__ __forceinline__ void cp_async16(uint32_t dst, const void* src) {
    asm volatile("cp.async.cg.shared.global [%0], [%1], 16;" :: "r"(dst), "l"(src));
}
__device__ __forceinline__ void ldsm_x4(uint32_t* r, uint32_t addr) {
    asm volatile("ldmatrix.sync.aligned.m8n8.x4.shared.b16 {%0,%1,%2,%3}, [%4];"
                 : "=r"(r[0]), "=r"(r[1]), "=r"(r[2]), "=r"(r[3]) : "r"(addr));
}
__device__ __forceinline__ void mma16816(float* d, const uint32_t* a, const uint32_t* b) {
    asm volatile(
        "mma.sync.aligned.m16n8k16.row.col.f32.f16.f16.f32 "
        "{%0,%1,%2,%3}, {%4,%5,%6,%7}, {%8,%9}, {%0,%1,%2,%3};"
        : "+f"(d[0]), "+f"(d[1]), "+f"(d[2]), "+f"(d[3])
        : "r"(a[0]), "r"(a[1]), "r"(a[2]), "r"(a[3]), "r"(b[0]), "r"(b[1]));
}

union Pack4 { __half b[4]; uint2 u; };
__device__ __forceinline__ void split1(float v, __half& h, __half& l) {
    h = __float2half_rn(v);
    l = __float2half_rn(v - __half2float(h));
}

// ---------------- convert: fp32 -> fp16 hi/lo (elementwise) ------------------
__global__ void conv_hl(const float4* __restrict__ in,
                        __half* __restrict__ oh, __half* __restrict__ ol)
{
    long i = (long)blockIdx.x * 256 + threadIdx.x;
    float4 v = in[i];
    Pack4 h, l;
    split1(v.x, h.b[0], l.b[0]);
    split1(v.y, h.b[1], l.b[1]);
    split1(v.z, h.b[2], l.b[2]);
    split1(v.w, h.b[3], l.b[3]);
    ((uint2*)oh)[i] = h.u;
    ((uint2*)ol)[i] = l.u;
}

// ---------------- transpose + split: in[R][C] -> out[C][R] hi/lo -------------
__global__ void transpose_hl(const float* __restrict__ in, long sIn, int R, int C,
                             __half* __restrict__ oh, __half* __restrict__ ol,
                             long sOut)
{
    __shared__ float t[32][33];
    in += (long)blockIdx.z * sIn;
    oh += (long)blockIdx.z * sOut;
    ol += (long)blockIdx.z * sOut;
    int c0 = blockIdx.x * 32, r0 = blockIdx.y * 32;
    int tx = threadIdx.x & 31, ty = threadIdx.x >> 5;  // 256 threads -> ty 0..7
    #pragma unroll
    for (int j = 0; j < 4; j++)
        t[ty + j * 8][tx] = in[(long)(r0 + ty + j * 8) * C + c0 + tx];
    __syncthreads();
    int c = threadIdx.x >> 3, g = threadIdx.x & 7;
    int rr = g * 4;
    Pack4 h, l;
    #pragma unroll
    for (int q = 0; q < 4; q++) split1(t[rr + q][c], h.b[q], l.b[q]);
    *(uint2*)(oh + (long)(c0 + c) * R + r0 + rr) = h.u;
    *(uint2*)(ol + (long)(c0 + c) * R + r0 + rr) = l.u;
}

// ---------------- bias: bias1[b,s] = x1[b,s,:].W1 ; bias2[b,t] = x2[b,t,:].W2
__global__ void bias_kernel(const float* __restrict__ x1, const float* __restrict__ x2,
                            const float* __restrict__ W1, const float* __restrict__ W2)
{
    int warp = (blockIdx.x * blockDim.x + threadIdx.x) >> 5;
    int lane = threadIdx.x & 31;
    const int total = BB * SS;
    const float* x; const float* W; float* out; int row;
    if (warp < total) { x = x1; W = W1; out = g_bias1; row = warp; }
    else              { x = x2; W = W2; out = g_bias2; row = warp - total; }
    const float4* xr = (const float4*)(x + (long)row * DD);
    const float4* W4 = (const float4*)W;
    float s = 0.f;
    #pragma unroll
    for (int i = lane; i < DD / 4; i += 32) {
        float4 a = xr[i], w = W4[i];
        s += a.x * w.x + a.y * w.y + a.z * w.z + a.w * w.w;
    }
    #pragma unroll
    for (int o = 16; o; o >>= 1) s += __shfl_xor_sync(0xffffffffu, s, o);
    if (lane == 0) out[row] = s;
}

// ---------------- mma.sync split-fp16 GEMM -----------------------------------
// TERMS=3: C = Ah@Bh + Ah@Bl + Al@Bh  (A has hi/lo planes)      [logits path]
// TERMS=2: C = Ah@Bh + Ah@Bl          (A single plane, e.g. P)  [output path]
// Block tile 128x128, BK=32, 8 warps (2M x 4N), warp tile 64x32.
// EPI 0: fp32 C.  EPI 1: fp16 hi/lo C.  EPI 2: fp32 C + biasR + biasC.
#define RSTRIDE 80                     // bytes per smem row (32 fp16 pad-> 40)
#define TILEB   (128 * RSTRIDE)        // 10240 B

template <int EPI, int TERMS>
__global__ void __launch_bounds__(256) gemm_tc(
    const __half* __restrict__ Ah, const __half* __restrict__ Al, long sA, int lda,
    const __half* __restrict__ Bh, const __half* __restrict__ Bl, long sB, int ldb,
    int K,
    float* __restrict__ C, __half* __restrict__ Ch, __half* __restrict__ Cl,
    long sC, int ldc,
    const float* __restrict__ biasR, const float* __restrict__ biasC, int Mtot, int Ntot)
{
    constexpr int NPL = (TERMS == 3) ? 4 : 3;           // planes per stage
    constexpr int STAGEB = NPL * TILEB;

    extern __shared__ char smem[];
    const uint32_t sbase = smem_to_u32(smem);
    const int tid = threadIdx.x;
    const int lane = tid & 31;
    const int wm = (tid >> 5) >> 2, wn = (tid >> 5) & 3;
    const int bm = blockIdx.y * 128, bn = blockIdx.x * 128, bz = blockIdx.z;

    const __half* a0 = Ah + (long)bz * sA;
    const __half* a1 = (TERMS == 3) ? (Al + (long)bz * sA) : nullptr;
    const __half* b0 = Bh + (long)bz * sB;
    const __half* b1 = Bl + (long)bz * sB;

    const int ldrow = tid >> 2;          // 0..63
    const int lds   = tid & 3;           // 16B seg

    float acc[4][4][4];
    #pragma unroll
    for (int i = 0; i < 4; i++)
        #pragma unroll
        for (int j = 0; j < 4; j++)
            #pragma unroll
            for (int q = 0; q < 4; q++) acc[i][j][q] = 0.f;

    const int NC = K >> 5;

    // plane order: [Ah (Al) Bh Bl]
    #define LOAD_STAGE(cc, st) do {                                            \
        uint32_t dst0 = sbase + (st) * STAGEB;                                 \
        int k0 = (cc) << 5;                                                    \
        _Pragma("unroll")                                                      \
        for (int q = 0; q < 2 * NPL; q++) {                                    \
            const int pl  = q >> 1;                                            \
            const int row = ((q & 1) << 6) + ldrow;                            \
            const int aPl = (TERMS == 3) ? 2 : 1;                              \
            const __half* sp = (pl < aPl)                                      \
                               ? ((pl == 0) ? a0 : a1)                         \
                               : ((pl == aPl) ? b0 : b1);                      \
            const int rb = (pl < aPl) ? bm : bn;                               \
            const int ld = (pl < aPl) ? lda : ldb;                             \
            cp_async16(dst0 + pl * TILEB + row * RSTRIDE + lds * 16,           \
                       sp + (long)(rb + row) * ld + k0 + lds * 8);             \
        }                                                                      \
        asm volatile("cp.async.commit_group;");                                \
    } while (0)

    LOAD_STAGE(0, 0);

    const int lr = lane & 15;
    const int lc = (lane >> 4) << 3;

    for (int c = 0; c < NC; c++) {
        if (c + 1 < NC) {
            LOAD_STAGE(c + 1, (c + 1) & 1);
            asm volatile("cp.async.wait_group 1;");
        } else {
            asm volatile("cp.async.wait_group 0;");
        }
        __syncthreads();

        uint32_t sAh = sbase + (c & 1) * STAGEB;
        uint32_t sAl = sAh + TILEB;                       // valid if TERMS==3
        uint32_t sBh = sAh + ((TERMS == 3) ? 2 : 1) * TILEB;
        uint32_t sBl = sBh + TILEB;

        #pragma unroll
        for (int kk = 0; kk < 2; kk++) {
            uint32_t fa_h[4][4], fa_l[4][4];
            #pragma unroll
            for (int mm = 0; mm < 4; mm++) {
                uint32_t off = (uint32_t)(wm * 64 + mm * 16 + lr) * RSTRIDE
                             + (uint32_t)(kk * 16 + lc) * 2;
                ldsm_x4(fa_h[mm], sAh + off);
                if (TERMS == 3) ldsm_x4(fa_l[mm], sAl + off);
            }
            uint32_t fb_h[2][4], fb_l[2][4];
            #pragma unroll
            for (int nn = 0; nn < 2; nn++) {
                uint32_t off = (uint32_t)(wn * 32 + nn * 16 + lr) * RSTRIDE
                             + (uint32_t)(kk * 16 + lc) * 2;
                ldsm_x4(fb_h[nn], sBh + off);
                ldsm_x4(fb_l[nn], sBl + off);
            }
            #pragma unroll
            for (int mm = 0; mm < 4; mm++) {
                #pragma unroll
                for (int nt = 0; nt < 4; nt++) {
                    uint32_t bh2[2] = { fb_h[nt >> 1][nt & 1], fb_h[nt >> 1][(nt & 1) + 2] };
                    uint32_t bl2[2] = { fb_l[nt >> 1][nt & 1], fb_l[nt >> 1][(nt & 1) + 2] };
                    float* d = acc[mm][nt];
                    mma16816(d, fa_h[mm], bh2);
                    mma16816(d, fa_h[mm], bl2);
                    if (TERMS == 3) mma16816(d, fa_l[mm], bh2);
                }
            }
        }
        __syncthreads();
    }

    // ---- epilogue
    const int er0 = bm + wm * 64 + (lane >> 2);
    const int ec0 = bn + wn * 32 + ((lane & 3) << 1);
    #pragma unroll
    for (int mm = 0; mm < 4; mm++) {
        #pragma unroll
        for (int nt = 0; nt < 4; nt++) {
            int row = er0 + mm * 16;
            int col = ec0 + nt * 8;
            float v0 = acc[mm][nt][0], v1 = acc[mm][nt][1];
            float v2 = acc[mm][nt][2], v3 = acc[mm][nt][3];
            if (EPI == 1) {
                __half h0, l0, h1, l1;
                long o = (long)bz * sC + (long)row * ldc + col;
                split1(v0, h0, l0); split1(v1, h1, l1);
                *(__half2*)(Ch + o) = __half2(h0, h1);
                *(__half2*)(Cl + o) = __half2(l0, l1);
                o += (long)8 * ldc;
                split1(v2, h0, l0); split1(v3, h1, l1);
                *(__half2*)(Ch + o) = __half2(h0, h1);
                *(__half2*)(Cl + o) = __half2(l0, l1);
            } else {
                if (EPI == 2) {
                    float bc0 = biasC[bz * Ntot + col], bc1 = biasC[bz * Ntot + col + 1];
                    float br0 = biasR[bz * Mtot + row], br8 = biasR[bz * Mtot + row + 8];
                    v0 += br0 + bc0; v1 += br0 + bc1;
                    v2 += br8 + bc0; v3 += br8 + bc1;
                }
                long o = (long)bz * sC + (long)row * ldc + col;
                *(float2*)(C + o) = make_float2(v0, v1);
                *(float2*)(C + o + (long)8 * ldc) = make_float2(v2, v3);
            }
        }
    }
}

// ---------------- softmax stats ---------------------------------------------
__global__ void row_stats_kernel()
{
    int row = blockIdx.x;
    const float4* a = (const float4*)(g_A + (long)row * SS);
    int tid = threadIdx.x;
    float4 v = a[tid];
    float m = fmaxf(fmaxf(v.x, v.y), fmaxf(v.z, v.w));
    #pragma unroll
    for (int o = 16; o; o >>= 1) m = fmaxf(m, __shfl_xor_sync(0xffffffffu, m, o));
    __shared__ float sm[4], ssum[4];
    int w = tid >> 5, l = tid & 31;
    if (l == 0) sm[w] = m;
    __syncthreads();
    m = fmaxf(fmaxf(sm[0], sm[1]), fmaxf(sm[2], sm[3]));
    float s = __expf(v.x - m) + __expf(v.y - m) + __expf(v.z - m) + __expf(v.w - m);
    #pragma unroll
    for (int o = 16; o; o >>= 1) s += __shfl_xor_sync(0xffffffffu, s, o);
    if (l == 0) ssum[w] = s;
    __syncthreads();
    s = ssum[0] + ssum[1] + ssum[2] + ssum[3];
    if (tid == 0) { g_rowmax[row] = m; g_rowrs[row] = 1.0f / s; }
}

__global__ void col_stats_kernel()
{
    int b = blockIdx.x >> 2;
    int t = ((blockIdx.x & 3) << 7) + threadIdx.x;
    const float* a = g_A + (long)b * SS * SS + t;
    float m = -1e30f;
    #pragma unroll 8
    for (int s = 0; s < SS; s++) m = fmaxf(m, a[(long)s * SS]);
    float sum = 0.f;
    #pragma unroll 8
    for (int s = 0; s < SS; s++) sum += __expf(a[(long)s * SS] - m);
    g_colmax[b * SS + t] = m;
    g_colrs [b * SS + t] = 1.0f / sum;
}

// ---------------- probabilities: P1 (fp16) and P2^T (fp16) -------------------
__global__ void prob_kernel()
{
    __shared__ float p2t[64 * 65];
    int b = blockIdx.z;
    int bs0 = blockIdx.y * 64, bt0 = blockIdx.x * 64;
    const float* A = g_A + (long)b * SS * SS;
    int tid = threadIdx.x;

    #pragma unroll
    for (int it = 0; it < 4; it++) {
        int idx = tid + it * 256;
        int r = idx >> 4, c4 = idx & 15;
        int s = bs0 + r;
        float4 v = *(const float4*)(A + (long)s * SS + bt0 + c4 * 4);
        float rm = g_rowmax[b * SS + s];
        float rr = g_rowrs [b * SS + s];
        const float4 cm = *(const float4*)(g_colmax + b * SS + bt0 + c4 * 4);
        const float4 cr = *(const float4*)(g_colrs  + b * SS + bt0 + c4 * 4);
        Pack4 h;
        h.b[0] = __float2half_rn(__expf(v.x - cm.x) * cr.x);
        h.b[1] = __float2half_rn(__expf(v.y - cm.y) * cr.y);
        h.b[2] = __float2half_rn(__expf(v.z - cm.z) * cr.z);
        h.b[3] = __float2half_rn(__expf(v.w - cm.w) * cr.w);
        long o1 = (long)b * SS * SS + (long)s * SS + bt0 + c4 * 4;
        *(uint2*)(g_P1 + o1) = h.u;
        float p2v[4] = { __expf(v.x - rm) * rr, __expf(v.y - rm) * rr,
                         __expf(v.z - rm) * rr, __expf(v.w - rm) * rr };
        #pragma unroll
        for (int q = 0; q < 4; q++) p2t[(c4 * 4 + q) * 65 + r] = p2v[q];
    }
    __syncthreads();
    int c = tid >> 2, g = tid & 3;
    #pragma unroll
    for (int j = 0; j < 4; j++) {
        int rr0 = g * 16 + j * 4;
        Pack4 h;
        #pragma unroll
        for (int q = 0; q < 4; q++) h.b[q] = __float2half_rn(p2t[c * 65 + rr0 + q]);
        long o = (long)b * SS * SS + (long)(bt0 + c) * SS + bs0 + rr0;
        *(uint2*)(g_P2T + o) = h.u;
    }
}

// ---------------- launch -----------------------------------------------------
extern "C" void kernel_launch(void* const* d_in, const int* in_sizes, int n_in,
                              void* d_out, int out_size)
{
    const float* x1 = (const float*)d_in[0];
    const float* x2 = (const float*)d_in[1];
    const float* Wc = (const float*)d_in[2];
    const float* W1 = (const float*)d_in[3];
    const float* W2 = (const float*)d_in[4];
    float* out1 = (float*)d_out;
    float* out2 = out1 + N_SD;

    __half *x1h, *x1l, *WcTh, *WcTl, *x2rh, *x2rl, *x2Th, *x2Tl, *x1Th, *x1Tl;
    __half *x1wh, *x1wl, *P1, *P2T;
    float *pA, *pb1, *pb2;
    cudaGetSymbolAddress((void**)&x1h,  g_x1h);
    cudaGetSymbolAddress((void**)&x1l,  g_x1l);
    cudaGetSymbolAddress((void**)&WcTh, g_WcTh);
    cudaGetSymbolAddress((void**)&WcTl, g_WcTl);
    cudaGetSymbolAddress((void**)&x2rh, g_x2rh);
    cudaGetSymbolAddress((void**)&x2rl, g_x2rl);
    cudaGetSymbolAddress((void**)&x2Th, g_x2Th);
    cudaGetSymbolAddress((void**)&x2Tl, g_x2Tl);
    cudaGetSymbolAddress((void**)&x1Th, g_x1Th);
    cudaGetSymbolAddress((void**)&x1Tl, g_x1Tl);
    cudaGetSymbolAddress((void**)&x1wh, g_x1wh);
    cudaGetSymbolAddress((void**)&x1wl, g_x1wl);
    cudaGetSymbolAddress((void**)&P1,   g_P1);
    cudaGetSymbolAddress((void**)&P2T,  g_P2T);
    cudaGetSymbolAddress((void**)&pA,   g_A);
    cudaGetSymbolAddress((void**)&pb1,  g_bias1);
    cudaGetSymbolAddress((void**)&pb2,  g_bias2);

    const int SMEM_T3 = 2 * 4 * TILEB;   // 81920
    const int SMEM_T2 = 2 * 3 * TILEB;   // 61440
    cudaFuncSetAttribute(gemm_tc<1, 3>, cudaFuncAttributeMaxDynamicSharedMemorySize, SMEM_T3);
    cudaFuncSetAttribute(gemm_tc<2, 3>, cudaFuncAttributeMaxDynamicSharedMemorySize, SMEM_T3);
    cudaFuncSetAttribute(gemm_tc<0, 2>, cudaFuncAttributeMaxDynamicSharedMemorySize, SMEM_T2);

    const long sSD = (long)SS * DD;
    const long sSq = (long)SS * SS;

    // converts / transposes
    conv_hl<<<(int)(N_SD / 4 / 256), 256>>>((const float4*)x1, x1h, x1l);
    transpose_hl<<<dim3(DD / 32, DD / 32, 1), 256>>>(Wc, 0, DD, DD, WcTh, WcTl, 0);
    transpose_hl<<<dim3(SS / 32, DD / 32, BB), 256>>>(x2, sSD, DD, SS, x2rh, x2rl, sSD);
    transpose_hl<<<dim3(DD / 32, SS / 32, BB), 256>>>(x2, sSD, SS, DD, x2Th, x2Tl, sSD);
    transpose_hl<<<dim3(DD / 32, SS / 32, BB), 256>>>(x1, sSD, SS, DD, x1Th, x1Tl, sSD);
    bias_kernel<<<(2 * BB * SS) / 8, 256>>>(x1, x2, W1, W2);

    // G1: x1w = x1 @ Wc  (M=512, N=768, K=768) -> fp16 hi/lo epilogue (3-term)
    gemm_tc<1, 3><<<dim3(DD / 128, SS / 128, BB), 256, SMEM_T3>>>(
        x1h, x1l, sSD, DD, WcTh, WcTl, 0, DD, DD,
        nullptr, x1wh, x1wl, sSD, DD, nullptr, nullptr, SS, DD);

    // G3: A = x1w @ x2r^T + biases  (M=512, N=512, K=768) -> fp32 + bias (3-term)
    gemm_tc<2, 3><<<dim3(SS / 128, SS / 128, BB), 256, SMEM_T3>>>(
        x1wh, x1wl, sSD, DD, x2rh, x2rl, sSD, DD, DD,
        pA, nullptr, nullptr, sSq, SS, pb1, pb2, SS, SS);

    row_stats_kernel<<<BB * SS, 128>>>();
    col_stats_kernel<<<BB * 4, 128>>>();
    prob_kernel<<<dim3(SS / 64, SS / 64, BB), 256>>>();

    // G5: f_x1 = P1 @ x2  (M=512, N=768, K=512)  2-term: P single plane
    gemm_tc<0, 2><<<dim3(DD / 128, SS / 128, BB), 256, SMEM_T2>>>(
        P1, nullptr, sSq, SS, x2Th, x2Tl, sSD, SS, SS,
        out1, nullptr, nullptr, sSD, DD, nullptr, nullptr, SS, DD);

    // G6: f_x2 = P2^T @ x1  (M=512, N=768, K=512)  2-term: P single plane
    gemm_tc<0, 2><<<dim3(DD / 128, SS / 128, BB), 256, SMEM_T2>>>(
        P2T, nullptr, sSq, SS, x1Th, x1Tl, sSD, SS, SS,
        out2, nullptr, nullptr, sSD, DD, nullptr, nullptr, SS, DD);
}

// round 6
// speedup vs baseline: 1.5229x; 1.3347x over previous
#include <cuda_runtime.h>
#include <cuda_fp16.h>
#include <cstdint>

#define BB 32
#define SS 512
#define DD 768

static const long N_SD = (long)BB * SS * DD;   // 12,582,912

// ---------------- scratch (static device globals; no allocations) ----------
__device__ __half g_x1h [BB * SS * DD];   // fp16 hi of x1 (natural [s][d])
__device__ __half g_x1l [BB * SS * DD];
__device__ __half g_x2h [BB * SS * DD];   // fp16 hi of x2 (natural [t][d]; flat view = [e][t] too)
__device__ __half g_x2l [BB * SS * DD];
__device__ __half g_Wch [DD * DD];        // fp16 hi of Wc (natural [d][e])
__device__ __half g_Wcl [DD * DD];
__device__ __half g_x1wh[BB * SS * DD];   // x1w hi/lo (natural [s][e])
__device__ __half g_x1wl[BB * SS * DD];
__device__ __half g_P1  [BB * SS * SS];   // single-plane fp16 P1 [s][t]
__device__ __half g_P2T [BB * SS * SS];   // single-plane fp16 P2^T [t][s]
__device__ float g_A  [BB * SS * SS];     // fp32 logits
__device__ float g_rowmax[BB * SS];
__device__ float g_rowrs [BB * SS];
__device__ float g_colmax[BB * SS];
__device__ float g_colrs [BB * SS];
__device__ float g_bias1 [BB * SS];
__device__ float g_bias2 [BB * SS];

// ---------------- helpers ----------------------------------------------------
__device__ __forceinline__ uint32_t smem_to_u32(const void* p) {
    uint32_t a;
    asm("{ .reg .u64 t; cvta.to.shared.u64 t, %1; cvt.u32.u64 %0, t; }" : "=r"(a) : "l"(p));
    return a;
}
__device__ __forceinline__ void cp_async16(uint32_t dst, const void* src) {
    asm volatile("cp.async.cg.shared.global [%0], [%1], 16;" :: "r"(dst), "l"(src));
}
__device__ __forceinline__ void ldsm_x4(uint32_t* r, uint32_t addr) {
    asm volatile("ldmatrix.sync.aligned.m8n8.x4.shared.b16 {%0,%1,%2,%3}, [%4];"
                 : "=r"(r[0]), "=r"(r[1]), "=r"(r[2]), "=r"(r[3]) : "r"(addr));
}
__device__ __forceinline__ void ldsm_x4_t(uint32_t* r, uint32_t addr) {
    asm volatile("ldmatrix.sync.aligned.m8n8.x4.trans.shared.b16 {%0,%1,%2,%3}, [%4];"
                 : "=r"(r[0]), "=r"(r[1]), "=r"(r[2]), "=r"(r[3]) : "r"(addr));
}
__device__ __forceinline__ void mma16816(float* d, const uint32_t* a, const uint32_t* b) {
    asm volatile(
        "mma.sync.aligned.m16n8k16.row.col.f32.f16.f16.f32 "
        "{%0,%1,%2,%3}, {%4,%5,%6,%7}, {%8,%9}, {%0,%1,%2,%3};"
        : "+f"(d[0]), "+f"(d[1]), "+f"(d[2]), "+f"(d[3])
        : "r"(a[0]), "r"(a[1]), "r"(a[2]), "r"(a[3]), "r"(b[0]), "r"(b[1]));
}

union Pack4 { __half b[4]; uint2 u; };
__device__ __forceinline__ void split1(float v, __half& h, __half& l) {
    h = __float2half_rn(v);
    l = __float2half_rn(v - __half2float(h));
}

// ---------------- convert: fp32 -> fp16 hi/lo (elementwise) ------------------
__global__ void conv_hl(const float4* __restrict__ in,
                        __half* __restrict__ oh, __half* __restrict__ ol)
{
    long i = (long)blockIdx.x * 256 + threadIdx.x;
    float4 v = in[i];
    Pack4 h, l;
    split1(v.x, h.b[0], l.b[0]);
    split1(v.y, h.b[1], l.b[1]);
    split1(v.z, h.b[2], l.b[2]);
    split1(v.w, h.b[3], l.b[3]);
    ((uint2*)oh)[i] = h.u;
    ((uint2*)ol)[i] = l.u;
}

// ---------------- bias: bias1[b,s] = x1[b,s,:].W1 ; bias2[b,t] = x2[b,t,:].W2
__global__ void bias_kernel(const float* __restrict__ x1, const float* __restrict__ x2,
                            const float* __restrict__ W1, const float* __restrict__ W2)
{
    int warp = (blockIdx.x * blockDim.x + threadIdx.x) >> 5;
    int lane = threadIdx.x & 31;
    const int total = BB * SS;
    const float* x; const float* W; float* out; int row;
    if (warp < total) { x = x1; W = W1; out = g_bias1; row = warp; }
    else              { x = x2; W = W2; out = g_bias2; row = warp - total; }
    const float4* xr = (const float4*)(x + (long)row * DD);
    const float4* W4 = (const float4*)W;
    float s = 0.f;
    #pragma unroll
    for (int i = lane; i < DD / 4; i += 32) {
        float4 a = xr[i], w = W4[i];
        s += a.x * w.x + a.y * w.y + a.z * w.z + a.w * w.w;
    }
    #pragma unroll
    for (int o = 16; o; o >>= 1) s += __shfl_xor_sync(0xffffffffu, s, o);
    if (lane == 0) out[row] = s;
}

// ---------------- mma.sync split-fp16 GEMM -----------------------------------
// A natural [M][K] (hi + optional lo plane); B natural [K][N] (hi+lo planes),
// loaded via ldmatrix.trans (no pre-transpose needed).
// TERMS=3: C = Ah@Bh + Ah@Bl + Al@Bh   [logits path]
// TERMS=2: C = Ah@Bh + Ah@Bl           [output path, A = P]
// Block tile 128x128, BK=32, 8 warps (2M x 4N), warp tile 64x32.
// EPI 0: fp32 C.  EPI 1: fp16 hi/lo C.  EPI 2: fp32 C + biasR + biasC.
#define TILEA   (128 * 80)   // A plane: 128 rows x 32 fp16, pad to 40 -> 10240 B
#define TILEB2  (32 * 256)   // B plane: 32 k-rows x 128 fp16 = 8192 B (swizzled)

template <int EPI, int TERMS>
__global__ void __launch_bounds__(256) gemm_tc(
    const __half* __restrict__ Ah, const __half* __restrict__ Al, long sA, int lda,
    const __half* __restrict__ Bh, const __half* __restrict__ Bl, long sB, int ldb,
    int K,
    float* __restrict__ C, __half* __restrict__ Ch, __half* __restrict__ Cl,
    long sC, int ldc,
    const float* __restrict__ biasR, const float* __restrict__ biasC, int Mtot, int Ntot)
{
    constexpr int NA = (TERMS == 3) ? 2 : 1;
    constexpr int STAGEB = NA * TILEA + 2 * TILEB2;

    extern __shared__ char smem[];
    const uint32_t sbase = smem_to_u32(smem);
    const int tid = threadIdx.x;
    const int lane = tid & 31;
    const int wm = (tid >> 5) >> 2, wn = (tid >> 5) & 3;
    const int bm = blockIdx.y * 128, bn = blockIdx.x * 128, bz = blockIdx.z;

    const __half* aP[2] = { Ah + (long)bz * sA,
                            (TERMS == 3) ? (Al + (long)bz * sA) : nullptr };
    const __half* bP[2] = { Bh + (long)bz * sB, Bl + (long)bz * sB };

    float acc[4][4][4];
    #pragma unroll
    for (int i = 0; i < 4; i++)
        #pragma unroll
        for (int j = 0; j < 4; j++)
            #pragma unroll
            for (int q = 0; q < 4; q++) acc[i][j][q] = 0.f;

    const int NC = K >> 5;

    #define LOAD_STAGE(cc, st) do {                                            \
        uint32_t dst0 = sbase + (st) * STAGEB;                                 \
        int k0 = (cc) << 5;                                                    \
        _Pragma("unroll")                                                      \
        for (int p = 0; p < NA; p++)                                           \
            _Pragma("unroll")                                                  \
            for (int h = 0; h < 2; h++) {                                      \
                int slot = tid + h * 256;                                      \
                int row = slot >> 2, seg = slot & 3;                           \
                cp_async16(dst0 + p * TILEA + row * 80 + seg * 16,             \
                           aP[p] + (long)(bm + row) * lda + k0 + seg * 8);     \
            }                                                                  \
        _Pragma("unroll")                                                      \
        for (int p = 0; p < 2; p++)                                            \
            _Pragma("unroll")                                                  \
            for (int h = 0; h < 2; h++) {                                      \
                int slot = tid + h * 256;                                      \
                int row = slot >> 4, seg = slot & 15;                          \
                uint32_t bo = (uint32_t)(row << 8) + (uint32_t)(seg << 4);     \
                bo ^= (uint32_t)(row & 7) << 4;                                \
                cp_async16(dst0 + NA * TILEA + p * TILEB2 + bo,                \
                           bP[p] + (long)(k0 + row) * ldb + bn + seg * 8);     \
            }                                                                  \
        asm volatile("cp.async.commit_group;");                                \
    } while (0)

    LOAD_STAGE(0, 0);

    const int lr = lane & 15;              // A frag row
    const int lc = (lane >> 4) << 3;       // A frag k-col
    const int g8  = lane >> 3;
    const int rowp = ((g8 & 1) << 3) + (lane & 7);   // 0..15 (k within 16)
    const int cs8  = (g8 >> 1) << 3;                 // 0 or 8 (n within 16)

    for (int c = 0; c < NC; c++) {
        if (c + 1 < NC) {
            LOAD_STAGE(c + 1, (c + 1) & 1);
            asm volatile("cp.async.wait_group 1;");
        } else {
            asm volatile("cp.async.wait_group 0;");
        }
        __syncthreads();

        uint32_t sAh = sbase + (c & 1) * STAGEB;
        uint32_t sAl = sAh + TILEA;                  // valid if TERMS==3
        uint32_t sBh = sbase + (c & 1) * STAGEB + NA * TILEA;
        uint32_t sBl = sBh + TILEB2;

        #pragma unroll
        for (int kk = 0; kk < 2; kk++) {
            uint32_t fa_h[4][4], fa_l[4][4];
            #pragma unroll
            for (int mm = 0; mm < 4; mm++) {
                uint32_t off = (uint32_t)(wm * 64 + mm * 16 + lr) * 80
                             + (uint32_t)(kk * 16 + lc) * 2;
                ldsm_x4(fa_h[mm], sAh + off);
                if (TERMS == 3) ldsm_x4(fa_l[mm], sAl + off);
            }
            uint32_t fb_h[2][4], fb_l[2][4];
            #pragma unroll
            for (int nn = 0; nn < 2; nn++) {
                uint32_t koff = (uint32_t)(kk * 16 + rowp);
                uint32_t bo = (koff << 8) + (uint32_t)(wn * 32 + nn * 16 + cs8) * 2;
                bo ^= (koff & 7) << 4;
                ldsm_x4_t(fb_h[nn], sBh + bo);
                ldsm_x4_t(fb_l[nn], sBl + bo);
            }
            #pragma unroll
            for (int mm = 0; mm < 4; mm++) {
                #pragma unroll
                for (int nt = 0; nt < 4; nt++) {
                    const int nn = nt >> 1, n2 = nt & 1;
                    uint32_t bh2[2] = { fb_h[nn][2 * n2], fb_h[nn][2 * n2 + 1] };
                    uint32_t bl2[2] = { fb_l[nn][2 * n2], fb_l[nn][2 * n2 + 1] };
                    float* d = acc[mm][nt];
                    mma16816(d, fa_h[mm], bh2);
                    mma16816(d, fa_h[mm], bl2);
                    if (TERMS == 3) mma16816(d, fa_l[mm], bh2);
                }
            }
        }
        __syncthreads();
    }

    // ---- epilogue
    const int er0 = bm + wm * 64 + (lane >> 2);
    const int ec0 = bn + wn * 32 + ((lane & 3) << 1);
    #pragma unroll
    for (int mm = 0; mm < 4; mm++) {
        #pragma unroll
        for (int nt = 0; nt < 4; nt++) {
            int row = er0 + mm * 16;
            int col = ec0 + nt * 8;
            float v0 = acc[mm][nt][0], v1 = acc[mm][nt][1];
            float v2 = acc[mm][nt][2], v3 = acc[mm][nt][3];
            if (EPI == 1) {
                __half h0, l0, h1, l1;
                long o = (long)bz * sC + (long)row * ldc + col;
                split1(v0, h0, l0); split1(v1, h1, l1);
                *(__half2*)(Ch + o) = __half2(h0, h1);
                *(__half2*)(Cl + o) = __half2(l0, l1);
                o += (long)8 * ldc;
                split1(v2, h0, l0); split1(v3, h1, l1);
                *(__half2*)(Ch + o) = __half2(h0, h1);
                *(__half2*)(Cl + o) = __half2(l0, l1);
            } else {
                if (EPI == 2) {
                    float bc0 = biasC[bz * Ntot + col], bc1 = biasC[bz * Ntot + col + 1];
                    float br0 = biasR[bz * Mtot + row], br8 = biasR[bz * Mtot + row + 8];
                    v0 += br0 + bc0; v1 += br0 + bc1;
                    v2 += br8 + bc0; v3 += br8 + bc1;
                }
                long o = (long)bz * sC + (long)row * ldc + col;
                *(float2*)(C + o) = make_float2(v0, v1);
                *(float2*)(C + o + (long)8 * ldc) = make_float2(v2, v3);
            }
        }
    }
}

// ---------------- softmax stats ---------------------------------------------
__global__ void row_stats_kernel()
{
    int row = blockIdx.x;
    const float4* a = (const float4*)(g_A + (long)row * SS);
    int tid = threadIdx.x;
    float4 v = a[tid];
    float m = fmaxf(fmaxf(v.x, v.y), fmaxf(v.z, v.w));
    #pragma unroll
    for (int o = 16; o; o >>= 1) m = fmaxf(m, __shfl_xor_sync(0xffffffffu, m, o));
    __shared__ float sm[4], ssum[4];
    int w = tid >> 5, l = tid & 31;
    if (l == 0) sm[w] = m;
    __syncthreads();
    m = fmaxf(fmaxf(sm[0], sm[1]), fmaxf(sm[2], sm[3]));
    float s = __expf(v.x - m) + __expf(v.y - m) + __expf(v.z - m) + __expf(v.w - m);
    #pragma unroll
    for (int o = 16; o; o >>= 1) s += __shfl_xor_sync(0xffffffffu, s, o);
    if (l == 0) ssum[w] = s;
    __syncthreads();
    s = ssum[0] + ssum[1] + ssum[2] + ssum[3];
    if (tid == 0) { g_rowmax[row] = m; g_rowrs[row] = 1.0f / s; }
}

__global__ void col_stats_kernel()
{
    int b = blockIdx.x >> 2;
    int t = ((blockIdx.x & 3) << 7) + threadIdx.x;
    const float* a = g_A + (long)b * SS * SS + t;
    float m = -1e30f;
    #pragma unroll 8
    for (int s = 0; s < SS; s++) m = fmaxf(m, a[(long)s * SS]);
    float sum = 0.f;
    #pragma unroll 8
    for (int s = 0; s < SS; s++) sum += __expf(a[(long)s * SS] - m);
    g_colmax[b * SS + t] = m;
    g_colrs [b * SS + t] = 1.0f / sum;
}

// ---------------- probabilities: P1 (fp16) and P2^T (fp16) -------------------
__global__ void prob_kernel()
{
    __shared__ float p2t[64 * 65];
    int b = blockIdx.z;
    int bs0 = blockIdx.y * 64, bt0 = blockIdx.x * 64;
    const float* A = g_A + (long)b * SS * SS;
    int tid = threadIdx.x;

    #pragma unroll
    for (int it = 0; it < 4; it++) {
        int idx = tid + it * 256;
        int r = idx >> 4, c4 = idx & 15;
        int s = bs0 + r;
        float4 v = *(const float4*)(A + (long)s * SS + bt0 + c4 * 4);
        float rm = g_rowmax[b * SS + s];
        float rr = g_rowrs [b * SS + s];
        const float4 cm = *(const float4*)(g_colmax + b * SS + bt0 + c4 * 4);
        const float4 cr = *(const float4*)(g_colrs  + b * SS + bt0 + c4 * 4);
        Pack4 h;
        h.b[0] = __float2half_rn(__expf(v.x - cm.x) * cr.x);
        h.b[1] = __float2half_rn(__expf(v.y - cm.y) * cr.y);
        h.b[2] = __float2half_rn(__expf(v.z - cm.z) * cr.z);
        h.b[3] = __float2half_rn(__expf(v.w - cm.w) * cr.w);
        long o1 = (long)b * SS * SS + (long)s * SS + bt0 + c4 * 4;
        *(uint2*)(g_P1 + o1) = h.u;
        float p2v[4] = { __expf(v.x - rm) * rr, __expf(v.y - rm) * rr,
                         __expf(v.z - rm) * rr, __expf(v.w - rm) * rr };
        #pragma unroll
        for (int q = 0; q < 4; q++) p2t[(c4 * 4 + q) * 65 + r] = p2v[q];
    }
    __syncthreads();
    int c = tid >> 2, g = tid & 3;
    #pragma unroll
    for (int j = 0; j < 4; j++) {
        int rr0 = g * 16 + j * 4;
        Pack4 h;
        #pragma unroll
        for (int q = 0; q < 4; q++) h.b[q] = __float2half_rn(p2t[c * 65 + rr0 + q]);
        long o = (long)b * SS * SS + (long)(bt0 + c) * SS + bs0 + rr0;
        *(uint2*)(g_P2T + o) = h.u;
    }
}

// ---------------- launch -----------------------------------------------------
extern "C" void kernel_launch(void* const* d_in, const int* in_sizes, int n_in,
                              void* d_out, int out_size)
{
    const float* x1 = (const float*)d_in[0];
    const float* x2 = (const float*)d_in[1];
    const float* Wc = (const float*)d_in[2];
    const float* W1 = (const float*)d_in[3];
    const float* W2 = (const float*)d_in[4];
    float* out1 = (float*)d_out;
    float* out2 = out1 + N_SD;

    __half *x1h, *x1l, *x2h, *x2l, *Wch, *Wcl, *x1wh, *x1wl, *P1, *P2T;
    float *pA, *pb1, *pb2;
    cudaGetSymbolAddress((void**)&x1h,  g_x1h);
    cudaGetSymbolAddress((void**)&x1l,  g_x1l);
    cudaGetSymbolAddress((void**)&x2h,  g_x2h);
    cudaGetSymbolAddress((void**)&x2l,  g_x2l);
    cudaGetSymbolAddress((void**)&Wch,  g_Wch);
    cudaGetSymbolAddress((void**)&Wcl,  g_Wcl);
    cudaGetSymbolAddress((void**)&x1wh, g_x1wh);
    cudaGetSymbolAddress((void**)&x1wl, g_x1wl);
    cudaGetSymbolAddress((void**)&P1,   g_P1);
    cudaGetSymbolAddress((void**)&P2T,  g_P2T);
    cudaGetSymbolAddress((void**)&pA,   g_A);
    cudaGetSymbolAddress((void**)&pb1,  g_bias1);
    cudaGetSymbolAddress((void**)&pb2,  g_bias2);

    const int SMEM_T3 = 2 * (2 * TILEA + 2 * TILEB2);   // 73728
    const int SMEM_T2 = 2 * (1 * TILEA + 2 * TILEB2);   // 53248
    cudaFuncSetAttribute(gemm_tc<1, 3>, cudaFuncAttributeMaxDynamicSharedMemorySize, SMEM_T3);
    cudaFuncSetAttribute(gemm_tc<2, 3>, cudaFuncAttributeMaxDynamicSharedMemorySize, SMEM_T3);
    cudaFuncSetAttribute(gemm_tc<0, 2>, cudaFuncAttributeMaxDynamicSharedMemorySize, SMEM_T2);

    const long sSD = (long)SS * DD;
    const long sSq = (long)SS * SS;

    // hi/lo converts (no transposes needed anymore)
    conv_hl<<<(int)(N_SD / 4 / 256), 256>>>((const float4*)x1, x1h, x1l);
    conv_hl<<<(int)(N_SD / 4 / 256), 256>>>((const float4*)x2, x2h, x2l);
    conv_hl<<<(DD * DD / 4) / 256, 256>>>((const float4*)Wc, Wch, Wcl);
    bias_kernel<<<(2 * BB * SS) / 8, 256>>>(x1, x2, W1, W2);

    // G1: x1w = x1 @ Wc  (M=512,N=768,K=768); B = Wc natural [d][e]
    gemm_tc<1, 3><<<dim3(DD / 128, SS / 128, BB), 256, SMEM_T3>>>(
        x1h, x1l, sSD, DD, Wch, Wcl, 0, DD, DD,
        nullptr, x1wh, x1wl, sSD, DD, nullptr, nullptr, SS, DD);

    // G3: A = x1w @ x2r + biases (M=512,N=512,K=768); B = x2 flat viewed [e][t] (ldb=SS)
    gemm_tc<2, 3><<<dim3(SS / 128, SS / 128, BB), 256, SMEM_T3>>>(
        x1wh, x1wl, sSD, DD, x2h, x2l, sSD, SS, DD,
        pA, nullptr, nullptr, sSq, SS, pb1, pb2, SS, SS);

    row_stats_kernel<<<BB * SS, 128>>>();
    col_stats_kernel<<<BB * 4, 128>>>();
    prob_kernel<<<dim3(SS / 64, SS / 64, BB), 256>>>();

    // G5: f_x1 = P1 @ x2 (M=512,N=768,K=512); B = x2 natural [t][d] (ldb=DD)
    gemm_tc<0, 2><<<dim3(DD / 128, SS / 128, BB), 256, SMEM_T2>>>(
        P1, nullptr, sSq, SS, x2h, x2l, sSD, DD, SS,
        out1, nullptr, nullptr, sSD, DD, nullptr, nullptr, SS, DD);

    // G6: f_x2 = P2^T @ x1 (M=512,N=768,K=512); B = x1 natural [s][d] (ldb=DD)
    gemm_tc<0, 2><<<dim3(DD / 128, SS / 128, BB), 256, SMEM_T2>>>(
        P2T, nullptr, sSq, SS, x1h, x1l, sSD, DD, SS,
        out2, nullptr, nullptr, sSD, DD, nullptr, nullptr, SS, DD);
}

// round 8
// speedup vs baseline: 1.6971x; 1.1143x over previous
#include <cuda_runtime.h>
#include <cuda_fp16.h>
#include <cstdint>

#define BB 32
#define SS 512
#define DD 768

static const long N_SD = (long)BB * SS * DD;   // 12,582,912

// ---------------- scratch (static device globals; no allocations) ----------
__device__ __half g_x1h [BB * SS * DD];   // fp16 hi of x1 (natural [s][d])
__device__ __half g_x1l [BB * SS * DD];
__device__ __half g_x2h [BB * SS * DD];   // fp16 hi of x2 (natural [t][d]; flat view = [e][t] too)
__device__ __half g_x2l [BB * SS * DD];
__device__ __half g_Wch [DD * DD];        // fp16 hi of Wc (natural [d][e])
__device__ __half g_Wcl [DD * DD];
__device__ __half g_x1wh[BB * SS * DD];   // x1w hi/lo (natural [s][e])
__device__ __half g_x1wl[BB * SS * DD];
__device__ __half g_P1  [BB * SS * SS];   // single-plane fp16 P1 [s][t]
__device__ __half g_P2T [BB * SS * SS];   // single-plane fp16 P2^T [t][s]
__device__ float g_A  [BB * SS * SS];     // fp32 logits
__device__ float g_rowmax[BB * SS];
__device__ float g_rowrs [BB * SS];
__device__ float g_colmax[BB * SS];
__device__ float g_colrs [BB * SS];
__device__ float g_bias1 [BB * SS];
__device__ float g_bias2 [BB * SS];
__device__ float g_pcm [BB * 8 * SS];     // per-chunk column max partials
__device__ float g_pcs [BB * 8 * SS];     // per-chunk column sum partials

// ---------------- helpers ----------------------------------------------------
__device__ __forceinline__ uint32_t smem_to_u32(const void* p) {
    uint32_t a;
    asm("{ .reg .u64 t; cvta.to.shared.u64 t, %1; cvt.u32.u64 %0, t; }" : "=r"(a) : "l"(p));
    return a;
}
__device__ __forceinline__ void cp_async16(uint32_t dst, const void* src) {
    asm volatile("cp.async.cg.shared.global [%0], [%1], 16;" :: "r"(dst), "l"(src));
}
__device__ __forceinline__ void ldsm_x4(uint32_t* r, uint32_t addr) {
    asm volatile("ldmatrix.sync.aligned.m8n8.x4.shared.b16 {%0,%1,%2,%3}, [%4];"
                 : "=r"(r[0]), "=r"(r[1]), "=r"(r[2]), "=r"(r[3]) : "r"(addr));
}
__device__ __forceinline__ void ldsm_x4_t(uint32_t* r, uint32_t addr) {
    asm volatile("ldmatrix.sync.aligned.m8n8.x4.trans.shared.b16 {%0,%1,%2,%3}, [%4];"
                 : "=r"(r[0]), "=r"(r[1]), "=r"(r[2]), "=r"(r[3]) : "r"(addr));
}
__device__ __forceinline__ void mma16816(float* d, const uint32_t* a, const uint32_t* b) {
    asm volatile(
        "mma.sync.aligned.m16n8k16.row.col.f32.f16.f16.f32 "
        "{%0,%1,%2,%3}, {%4,%5,%6,%7}, {%8,%9}, {%0,%1,%2,%3};"
        : "+f"(d[0]), "+f"(d[1]), "+f"(d[2]), "+f"(d[3])
        : "r"(a[0]), "r"(a[1]), "r"(a[2]), "r"(a[3]), "r"(b[0]), "r"(b[1]));
}

union Pack4 { __half b[4]; uint2 u; };
__device__ __forceinline__ void split1(float v, __half& h, __half& l) {
    h = __float2half_rn(v);
    l = __float2half_rn(v - __half2float(h));
}

// ---------------- fused convert + bias: one warp per row ---------------------
// Converts x -> hi/lo fp16 planes AND computes bias[row] = x[row,:].W in one read.
__global__ void conv_bias(const float* __restrict__ x1, const float* __restrict__ x2,
                          const float* __restrict__ W1, const float* __restrict__ W2)
{
    int gw = blockIdx.x * 8 + (threadIdx.x >> 5);
    int lane = threadIdx.x & 31;
    const int total = BB * SS;
    const float* x; const float* W; __half* oh; __half* ol; float* bout; int row;
    if (gw < total) { x = x1; W = W1; oh = g_x1h; ol = g_x1l; bout = g_bias1; row = gw; }
    else            { x = x2; W = W2; oh = g_x2h; ol = g_x2l; bout = g_bias2; row = gw - total; }

    const float4* xr = (const float4*)(x + (long)row * DD);
    const float4* W4 = (const float4*)W;
    uint2* ohp = (uint2*)(oh + (long)row * DD);
    uint2* olp = (uint2*)(ol + (long)row * DD);

    float s = 0.f;
    #pragma unroll
    for (int i = 0; i < 6; i++) {            // 192 float4 per row / 32 lanes
        int idx = i * 32 + lane;
        float4 a = xr[idx], wv = W4[idx];
        s += a.x * wv.x + a.y * wv.y + a.z * wv.z + a.w * wv.w;
        Pack4 h, l;
        split1(a.x, h.b[0], l.b[0]);
        split1(a.y, h.b[1], l.b[1]);
        split1(a.z, h.b[2], l.b[2]);
        split1(a.w, h.b[3], l.b[3]);
        ohp[idx] = h.u;
        olp[idx] = l.u;
    }
    #pragma unroll
    for (int o = 16; o; o >>= 1) s += __shfl_xor_sync(0xffffffffu, s, o);
    if (lane == 0) bout[row] = s;
}

// ---------------- convert: fp32 -> fp16 hi/lo (elementwise, for Wc) ----------
__global__ void conv_hl(const float4* __restrict__ in,
                        __half* __restrict__ oh, __half* __restrict__ ol)
{
    long i = (long)blockIdx.x * 256 + threadIdx.x;
    float4 v = in[i];
    Pack4 h, l;
    split1(v.x, h.b[0], l.b[0]);
    split1(v.y, h.b[1], l.b[1]);
    split1(v.z, h.b[2], l.b[2]);
    split1(v.w, h.b[3], l.b[3]);
    ((uint2*)oh)[i] = h.u;
    ((uint2*)ol)[i] = l.u;
}

// ---------------- mma.sync split-fp16 GEMM -----------------------------------
// A natural [M][K] (hi + optional lo plane); B natural [K][N] (hi+lo planes),
// loaded via ldmatrix.trans (no pre-transpose needed).
// TERMS=3: C = Ah@Bh + Ah@Bl + Al@Bh   [logits path]
// TERMS=2: C = Ah@Bh + Ah@Bl           [output path, A = P]
// Block tile 128x128, BK=32, 8 warps (2M x 4N), warp tile 64x32.
// EPI 0: fp32 C.  EPI 1: fp16 hi/lo C.  EPI 2: fp32 C + biasR + biasC.
#define TILEA   (128 * 80)   // A plane: 128 rows x 32 fp16, pad to 40 -> 10240 B
#define TILEB2  (32 * 256)   // B plane: 32 k-rows x 128 fp16 = 8192 B (swizzled)

template <int EPI, int TERMS>
__global__ void __launch_bounds__(256) gemm_tc(
    const __half* __restrict__ Ah, const __half* __restrict__ Al, long sA, int lda,
    const __half* __restrict__ Bh, const __half* __restrict__ Bl, long sB, int ldb,
    int K,
    float* __restrict__ C, __half* __restrict__ Ch, __half* __restrict__ Cl,
    long sC, int ldc,
    const float* __restrict__ biasR, const float* __restrict__ biasC, int Mtot, int Ntot)
{
    constexpr int NA = (TERMS == 3) ? 2 : 1;
    constexpr int STAGEB = NA * TILEA + 2 * TILEB2;

    extern __shared__ char smem[];
    const uint32_t sbase = smem_to_u32(smem);
    const int tid = threadIdx.x;
    const int lane = tid & 31;
    const int wm = (tid >> 5) >> 2, wn = (tid >> 5) & 3;
    const int bm = blockIdx.y * 128, bn = blockIdx.x * 128, bz = blockIdx.z;

    const __half* aP[2] = { Ah + (long)bz * sA,
                            (TERMS == 3) ? (Al + (long)bz * sA) : nullptr };
    const __half* bP[2] = { Bh + (long)bz * sB, Bl + (long)bz * sB };

    float acc[4][4][4];
    #pragma unroll
    for (int i = 0; i < 4; i++)
        #pragma unroll
        for (int j = 0; j < 4; j++)
            #pragma unroll
            for (int q = 0; q < 4; q++) acc[i][j][q] = 0.f;

    const int NC = K >> 5;

    #define LOAD_STAGE(cc, st) do {                                            \
        uint32_t dst0 = sbase + (st) * STAGEB;                                 \
        int k0 = (cc) << 5;                                                    \
        _Pragma("unroll")                                                      \
        for (int p = 0; p < NA; p++)                                           \
            _Pragma("unroll")                                                  \
            for (int h = 0; h < 2; h++) {                                      \
                int slot = tid + h * 256;                                      \
                int row = slot >> 2, seg = slot & 3;                           \
                cp_async16(dst0 + p * TILEA + row * 80 + seg * 16,             \
                           aP[p] + (long)(bm + row) * lda + k0 + seg * 8);     \
            }                                                                  \
        _Pragma("unroll")                                                      \
        for (int p = 0; p < 2; p++)                                            \
            _Pragma("unroll")                                                  \
            for (int h = 0; h < 2; h++) {                                      \
                int slot = tid + h * 256;                                      \
                int row = slot >> 4, seg = slot & 15;                          \
                uint32_t bo = (uint32_t)(row << 8) + (uint32_t)(seg << 4);     \
                bo ^= (uint32_t)(row & 7) << 4;                                \
                cp_async16(dst0 + NA * TILEA + p * TILEB2 + bo,                \
                           bP[p] + (long)(k0 + row) * ldb + bn + seg * 8);     \
            }                                                                  \
        asm volatile("cp.async.commit_group;");                                \
    } while (0)

    LOAD_STAGE(0, 0);

    const int lr = lane & 15;              // A frag row
    const int lc = (lane >> 4) << 3;       // A frag k-col
    const int g8  = lane >> 3;
    const int rowp = ((g8 & 1) << 3) + (lane & 7);   // 0..15 (k within 16)
    const int cs8  = (g8 >> 1) << 3;                 // 0 or 8 (n within 16)

    for (int c = 0; c < NC; c++) {
        if (c + 1 < NC) {
            LOAD_STAGE(c + 1, (c + 1) & 1);
            asm volatile("cp.async.wait_group 1;");
        } else {
            asm volatile("cp.async.wait_group 0;");
        }
        __syncthreads();

        uint32_t sAh = sbase + (c & 1) * STAGEB;
        uint32_t sAl = sAh + TILEA;                  // valid if TERMS==3
        uint32_t sBh = sbase + (c & 1) * STAGEB + NA * TILEA;
        uint32_t sBl = sBh + TILEB2;

        #pragma unroll
        for (int kk = 0; kk < 2; kk++) {
            uint32_t fa_h[4][4], fa_l[4][4];
            #pragma unroll
            for (int mm = 0; mm < 4; mm++) {
                uint32_t off = (uint32_t)(wm * 64 + mm * 16 + lr) * 80
                             + (uint32_t)(kk * 16 + lc) * 2;
                ldsm_x4(fa_h[mm], sAh + off);
                if (TERMS == 3) ldsm_x4(fa_l[mm], sAl + off);
            }
            uint32_t fb_h[2][4], fb_l[2][4];
            #pragma unroll
            for (int nn = 0; nn < 2; nn++) {
                uint32_t koff = (uint32_t)(kk * 16 + rowp);
                uint32_t bo = (koff << 8) + (uint32_t)(wn * 32 + nn * 16 + cs8) * 2;
                bo ^= (koff & 7) << 4;
                ldsm_x4_t(fb_h[nn], sBh + bo);
                ldsm_x4_t(fb_l[nn], sBl + bo);
            }
            #pragma unroll
            for (int mm = 0; mm < 4; mm++) {
                #pragma unroll
                for (int nt = 0; nt < 4; nt++) {
                    const int nn = nt >> 1, n2 = nt & 1;
                    uint32_t bh2[2] = { fb_h[nn][2 * n2], fb_h[nn][2 * n2 + 1] };
                    uint32_t bl2[2] = { fb_l[nn][2 * n2], fb_l[nn][2 * n2 + 1] };
                    float* d = acc[mm][nt];
                    mma16816(d, fa_h[mm], bh2);
                    mma16816(d, fa_h[mm], bl2);
                    if (TERMS == 3) mma16816(d, fa_l[mm], bh2);
                }
            }
        }
        __syncthreads();
    }

    // ---- epilogue
    const int er0 = bm + wm * 64 + (lane >> 2);
    const int ec0 = bn + wn * 32 + ((lane & 3) << 1);
    #pragma unroll
    for (int mm = 0; mm < 4; mm++) {
        #pragma unroll
        for (int nt = 0; nt < 4; nt++) {
            int row = er0 + mm * 16;
            int col = ec0 + nt * 8;
            float v0 = acc[mm][nt][0], v1 = acc[mm][nt][1];
            float v2 = acc[mm][nt][2], v3 = acc[mm][nt][3];
            if (EPI == 1) {
                __half h0, l0, h1, l1;
                long o = (long)bz * sC + (long)row * ldc + col;
                split1(v0, h0, l0); split1(v1, h1, l1);
                *(__half2*)(Ch + o) = __half2(h0, h1);
                *(__half2*)(Cl + o) = __half2(l0, l1);
                o += (long)8 * ldc;
                split1(v2, h0, l0); split1(v3, h1, l1);
                *(__half2*)(Ch + o) = __half2(h0, h1);
                *(__half2*)(Cl + o) = __half2(l0, l1);
            } else {
                if (EPI == 2) {
                    float bc0 = biasC[bz * Ntot + col], bc1 = biasC[bz * Ntot + col + 1];
                    float br0 = biasR[bz * Mtot + row], br8 = biasR[bz * Mtot + row + 8];
                    v0 += br0 + bc0; v1 += br0 + bc1;
                    v2 += br8 + bc0; v3 += br8 + bc1;
                }
                long o = (long)bz * sC + (long)row * ldc + col;
                *(float2*)(C + o) = make_float2(v0, v1);
                *(float2*)(C + o + (long)8 * ldc) = make_float2(v2, v3);
            }
        }
    }
}

// ---------------- fused softmax stats: one A read ----------------------------
// Block = (chunk of 64 rows) x 512 cols. Row stats complete per warp.
// Column stats: online-softmax partials per 64-row chunk -> g_pcm/g_pcs.
__global__ void __launch_bounds__(256) stats_fused()
{
    int b = blockIdx.y, chunk = blockIdx.x;
    int w = threadIdx.x >> 5, lane = threadIdx.x & 31;
    const float* A = g_A + (long)b * SS * SS;

    float cm[16], cs[16];
    #pragma unroll
    for (int q = 0; q < 16; q++) { cm[q] = -1e30f; cs[q] = 0.f; }

    #pragma unroll
    for (int r8 = 0; r8 < 8; r8++) {
        int s = chunk * 64 + w * 8 + r8;
        const float4* ar = (const float4*)(A + (long)s * SS);
        float v[16];
        #pragma unroll
        for (int it = 0; it < 4; it++) {
            float4 t4 = ar[it * 32 + lane];
            v[it * 4 + 0] = t4.x; v[it * 4 + 1] = t4.y;
            v[it * 4 + 2] = t4.z; v[it * 4 + 3] = t4.w;
        }
        // row stats
        float rm = v[0];
        #pragma unroll
        for (int q = 1; q < 16; q++) rm = fmaxf(rm, v[q]);
        #pragma unroll
        for (int o = 16; o; o >>= 1) rm = fmaxf(rm, __shfl_xor_sync(0xffffffffu, rm, o));
        float rs = 0.f;
        #pragma unroll
        for (int q = 0; q < 16; q++) rs += __expf(v[q] - rm);
        #pragma unroll
        for (int o = 16; o; o >>= 1) rs += __shfl_xor_sync(0xffffffffu, rs, o);
        if (lane == 0) { g_rowmax[b * SS + s] = rm; g_rowrs[b * SS + s] = 1.0f / rs; }
        // online column update
        #pragma unroll
        for (int q = 0; q < 16; q++) {
            float nm = fmaxf(cm[q], v[q]);
            cs[q] = cs[q] * __expf(cm[q] - nm) + __expf(v[q] - nm);
            cm[q] = nm;
        }
    }

    __shared__ float scm[8][SS], scs[8][SS];
    #pragma unroll
    for (int it = 0; it < 4; it++)
        #pragma unroll
        for (int q = 0; q < 4; q++) {
            int col = it * 128 + lane * 4 + q;
            scm[w][col] = cm[it * 4 + q];
            scs[w][col] = cs[it * 4 + q];
        }
    __syncthreads();

    #pragma unroll
    for (int j = 0; j < 2; j++) {
        int col = threadIdx.x + j * 256;
        float M = scm[0][col];
        #pragma unroll
        for (int ww = 1; ww < 8; ww++) M = fmaxf(M, scm[ww][col]);
        float S = 0.f;
        #pragma unroll
        for (int ww = 0; ww < 8; ww++) S += scs[ww][col] * __expf(scm[ww][col] - M);
        g_pcm[((long)b * 8 + chunk) * SS + col] = M;
        g_pcs[((long)b * 8 + chunk) * SS + col] = S;
    }
}

// combine 8 chunk partials per column -> final col stats
__global__ void stats_combine()
{
    int i = blockIdx.x * 256 + threadIdx.x;   // b*512 + t
    int b = i >> 9, t = i & 511;
    float M = -1e30f;
    #pragma unroll
    for (int c = 0; c < 8; c++) M = fmaxf(M, g_pcm[((long)b * 8 + c) * SS + t]);
    float S = 0.f;
    #pragma unroll
    for (int c = 0; c < 8; c++)
        S += g_pcs[((long)b * 8 + c) * SS + t] * __expf(g_pcm[((long)b * 8 + c) * SS + t] - M);
    g_colmax[b * SS + t] = M;
    g_colrs [b * SS + t] = 1.0f / S;
}

// ---------------- probabilities: P1 (fp16) and P2^T (fp16) -------------------
__global__ void prob_kernel()
{
    __shared__ float p2t[64 * 65];
    int b = blockIdx.z;
    int bs0 = blockIdx.y * 64, bt0 = blockIdx.x * 64;
    const float* A = g_A + (long)b * SS * SS;
    int tid = threadIdx.x;

    #pragma unroll
    for (int it = 0; it < 4; it++) {
        int idx = tid + it * 256;
        int r = idx >> 4, c4 = idx & 15;
        int s = bs0 + r;
        float4 v = *(const float4*)(A + (long)s * SS + bt0 + c4 * 4);
        float rm = g_rowmax[b * SS + s];
        float rr = g_rowrs [b * SS + s];
        const float4 cm = *(const float4*)(g_colmax + b * SS + bt0 + c4 * 4);
        const float4 cr = *(const float4*)(g_colrs  + b * SS + bt0 + c4 * 4);
        Pack4 h;
        h.b[0] = __float2half_rn(__expf(v.x - cm.x) * cr.x);
        h.b[1] = __float2half_rn(__expf(v.y - cm.y) * cr.y);
        h.b[2] = __float2half_rn(__expf(v.z - cm.z) * cr.z);
        h.b[3] = __float2half_rn(__expf(v.w - cm.w) * cr.w);
        long o1 = (long)b * SS * SS + (long)s * SS + bt0 + c4 * 4;
        *(uint2*)(g_P1 + o1) = h.u;
        float p2v[4] = { __expf(v.x - rm) * rr, __expf(v.y - rm) * rr,
                         __expf(v.z - rm) * rr, __expf(v.w - rm) * rr };
        #pragma unroll
        for (int q = 0; q < 4; q++) p2t[(c4 * 4 + q) * 65 + r] = p2v[q];
    }
    __syncthreads();
    int c = tid >> 2, g = tid & 3;
    #pragma unroll
    for (int j = 0; j < 4; j++) {
        int rr0 = g * 16 + j * 4;
        Pack4 h;
        #pragma unroll
        for (int q = 0; q < 4; q++) h.b[q] = __float2half_rn(p2t[c * 65 + rr0 + q]);
        long o = (long)b * SS * SS + (long)(bt0 + c) * SS + bs0 + rr0;
        *(uint2*)(g_P2T + o) = h.u;
    }
}

// ---------------- launch -----------------------------------------------------
extern "C" void kernel_launch(void* const* d_in, const int* in_sizes, int n_in,
                              void* d_out, int out_size)
{
    const float* x1 = (const float*)d_in[0];
    const float* x2 = (const float*)d_in[1];
    const float* Wc = (const float*)d_in[2];
    const float* W1 = (const float*)d_in[3];
    const float* W2 = (const float*)d_in[4];
    float* out1 = (float*)d_out;
    float* out2 = out1 + N_SD;

    __half *x1h, *x1l, *x2h, *x2l, *Wch, *Wcl, *x1wh, *x1wl, *P1, *P2T;
    float *pA, *pb1, *pb2;
    cudaGetSymbolAddress((void**)&x1h,  g_x1h);
    cudaGetSymbolAddress((void**)&x1l,  g_x1l);
    cudaGetSymbolAddress((void**)&x2h,  g_x2h);
    cudaGetSymbolAddress((void**)&x2l,  g_x2l);
    cudaGetSymbolAddress((void**)&Wch,  g_Wch);
    cudaGetSymbolAddress((void**)&Wcl,  g_Wcl);
    cudaGetSymbolAddress((void**)&x1wh, g_x1wh);
    cudaGetSymbolAddress((void**)&x1wl, g_x1wl);
    cudaGetSymbolAddress((void**)&P1,   g_P1);
    cudaGetSymbolAddress((void**)&P2T,  g_P2T);
    cudaGetSymbolAddress((void**)&pA,   g_A);
    cudaGetSymbolAddress((void**)&pb1,  g_bias1);
    cudaGetSymbolAddress((void**)&pb2,  g_bias2);

    const int SMEM_T3 = 2 * (2 * TILEA + 2 * TILEB2);   // 73728
    const int SMEM_T2 = 2 * (1 * TILEA + 2 * TILEB2);   // 53248
    cudaFuncSetAttribute(gemm_tc<1, 3>, cudaFuncAttributeMaxDynamicSharedMemorySize, SMEM_T3);
    cudaFuncSetAttribute(gemm_tc<2, 3>, cudaFuncAttributeMaxDynamicSharedMemorySize, SMEM_T3);
    cudaFuncSetAttribute(gemm_tc<0, 2>, cudaFuncAttributeMaxDynamicSharedMemorySize, SMEM_T2);

    const long sSD = (long)SS * DD;
    const long sSq = (long)SS * SS;

    // fused hi/lo converts + bias dots (one read of x1, x2)
    conv_bias<<<(2 * BB * SS) / 8, 256>>>(x1, x2, W1, W2);
    conv_hl<<<(DD * DD / 4) / 256, 256>>>((const float4*)Wc, Wch, Wcl);

    // G1: x1w = x1 @ Wc  (M=512,N=768,K=768); B = Wc natural [d][e]
    gemm_tc<1, 3><<<dim3(DD / 128, SS / 128, BB), 256, SMEM_T3>>>(
        x1h, x1l, sSD, DD, Wch, Wcl, 0, DD, DD,
        nullptr, x1wh, x1wl, sSD, DD, nullptr, nullptr, SS, DD);

    // G3: A = x1w @ x2r + biases (M=512,N=512,K=768); B = x2 flat viewed [e][t] (ldb=SS)
    gemm_tc<2, 3><<<dim3(SS / 128, SS / 128, BB), 256, SMEM_T3>>>(
        x1wh, x1wl, sSD, DD, x2h, x2l, sSD, SS, DD,
        pA, nullptr, nullptr, sSq, SS, pb1, pb2, SS, SS);

    // fused row+col stats (one A read) + tiny combine
    stats_fused<<<dim3(8, BB), 256>>>();
    stats_combine<<<(BB * SS) / 256, 256>>>();
    prob_kernel<<<dim3(SS / 64, SS / 64, BB), 256>>>();

    // G5: f_x1 = P1 @ x2 (M=512,N=768,K=512); B = x2 natural [t][d] (ldb=DD)
    gemm_tc<0, 2><<<dim3(DD / 128, SS / 128, BB), 256, SMEM_T2>>>(
        P1, nullptr, sSq, SS, x2h, x2l, sSD, DD, SS,
        out1, nullptr, nullptr, sSD, DD, nullptr, nullptr, SS, DD);

    // G6: f_x2 = P2^T @ x1 (M=512,N=768,K=512); B = x1 natural [s][d] (ldb=DD)
    gemm_tc<0, 2><<<dim3(DD / 128, SS / 128, BB), 256, SMEM_T2>>>(
        P2T, nullptr, sSq, SS, x1h, x1l, sSD, DD, SS,
        out2, nullptr, nullptr, sSD, DD, nullptr, nullptr, SS, DD);
}